// round 1
// baseline (speedup 1.0000x reference)
#include <cuda_runtime.h>
#include <math.h>

// Problem constants
#define N_ 2
#define LQ_ 4000
#define C_ 256
#define M_ 8
#define L_ 4
#define P_ 4
#define D_ 32
#define LIN_ 5440   // 64*64 + 32*32 + 16*16 + 8*8

// Scratch (static device globals; no allocation allowed)
__device__ float g_value[N_ * LIN_ * C_];   // [N, Lin, M, D]
__device__ float g_key  [N_ * LIN_ * C_];   // [N, Lin, M, D]
__device__ float g_q    [N_ * LQ_ * C_];    // [N, Lq, M, D]
__device__ float g_off  [N_ * LQ_ * C_];    // [N, Lq, M*L*P*2]
__device__ float g_att  [N_ * LQ_ * C_];    // [N, Lq, M, D]

// ---------------------------------------------------------------------------
// Generic fp32 GEMM: C[rows, 256] = A[rows, 256] @ W[256, 256] + bias
// 64x64 tile, BK=16, 256 threads, 4x4 register tile per thread.
// rows is always a multiple of 64 here (10880, 8000).
// ---------------------------------------------------------------------------
__global__ __launch_bounds__(256) void gemm_bias_256(
    const float* __restrict__ A, const float* __restrict__ W,
    const float* __restrict__ bias, float* __restrict__ Cout, int rows)
{
    __shared__ float As[16][68];   // [k][r]  (+4 pad)
    __shared__ float Bs[16][68];   // [k][c]

    const int tid = threadIdx.y * 16 + threadIdx.x;
    const int tx = threadIdx.x;           // 0..15 -> col group
    const int ty = threadIdx.y;           // 0..15 -> row group
    const int row0 = blockIdx.y * 64;
    const int col0 = blockIdx.x * 64;

    float acc[4][4];
#pragma unroll
    for (int i = 0; i < 4; i++)
#pragma unroll
        for (int j = 0; j < 4; j++) acc[i][j] = 0.0f;

    // A-tile load mapping: r = tid/4 (0..63), kq = tid%4 (float4 along K)
    const int ar = tid >> 2;
    const int akq = (tid & 3) * 4;
    // B-tile load mapping: k = tid/16 (0..15), cq = tid%16 (float4 along cols)
    const int bk = tid >> 4;
    const int bcq = (tid & 15) * 4;

    for (int k0 = 0; k0 < 256; k0 += 16) {
        // load A tile (64 x 16) transposed into As[k][r]
        float4 a4 = *reinterpret_cast<const float4*>(&A[(row0 + ar) * 256 + k0 + akq]);
        As[akq + 0][ar] = a4.x;
        As[akq + 1][ar] = a4.y;
        As[akq + 2][ar] = a4.z;
        As[akq + 3][ar] = a4.w;
        // load B tile (16 x 64)
        float4 b4 = *reinterpret_cast<const float4*>(&W[(k0 + bk) * 256 + col0 + bcq]);
        Bs[bk][bcq + 0] = b4.x;
        Bs[bk][bcq + 1] = b4.y;
        Bs[bk][bcq + 2] = b4.z;
        Bs[bk][bcq + 3] = b4.w;
        __syncthreads();

#pragma unroll
        for (int k = 0; k < 16; k++) {
            float a[4], b[4];
#pragma unroll
            for (int i = 0; i < 4; i++) a[i] = As[k][ty * 4 + i];
#pragma unroll
            for (int j = 0; j < 4; j++) b[j] = Bs[k][tx * 4 + j];
#pragma unroll
            for (int i = 0; i < 4; i++)
#pragma unroll
                for (int j = 0; j < 4; j++) acc[i][j] = fmaf(a[i], b[j], acc[i][j]);
        }
        __syncthreads();
    }

    float bb[4];
#pragma unroll
    for (int j = 0; j < 4; j++) bb[j] = bias[col0 + tx * 4 + j];
#pragma unroll
    for (int i = 0; i < 4; i++) {
        float4 o;
        o.x = acc[i][0] + bb[0];
        o.y = acc[i][1] + bb[1];
        o.z = acc[i][2] + bb[2];
        o.w = acc[i][3] + bb[3];
        *reinterpret_cast<float4*>(&Cout[(row0 + ty * 4 + i) * 256 + col0 + tx * 4]) = o;
    }
}

// ---------------------------------------------------------------------------
// Sampling + key-aware attention. One warp per (n, q, m); lane = channel d.
// ---------------------------------------------------------------------------
__global__ __launch_bounds__(256) void sample_attn_kernel(
    const float* __restrict__ ref)   // [N, Lq, L, 2]
{
    const int w = blockIdx.x * (blockDim.x >> 5) + (threadIdx.x >> 5);
    const int lane = threadIdx.x & 31;
    const int total = N_ * LQ_ * M_;
    if (w >= total) return;

    const int m  = w % M_;
    const int nq = w / M_;           // n*Lq + q
    const int n  = nq / LQ_;

    const float qd = g_q[(nq * M_ + m) * D_ + lane];
    const float* offp = g_off + nq * 256 + m * (L_ * P_ * 2);
    const float* refp = ref + nq * L_ * 2;

    const int   HWs[4]    = {64, 32, 16, 8};
    const int   starts[4] = {0, 4096, 5120, 5376};

    float logits[16];
    float svr[16];

#pragma unroll
    for (int l = 0; l < L_; l++) {
        const float rx = refp[l * 2 + 0];
        const float ry = refp[l * 2 + 1];
        const int HW = HWs[l];
        const float fHW = (float)HW;
        const float fx = rx * fHW - 0.5f;
        const float fy = ry * fHW - 0.5f;
        const int base_n = n * LIN_ + starts[l];
#pragma unroll
        for (int p = 0; p < P_; p++) {
            const int pi = l * P_ + p;
            const float x = fx + offp[pi * 2 + 0];
            const float y = fy + offp[pi * 2 + 1];
            const float x0f = floorf(x);
            const float y0f = floorf(y);
            const float txf = x - x0f;
            const float tyf = y - y0f;
            const int x0 = (int)x0f;
            const int y0 = (int)y0f;

            float sk = 0.0f, sv = 0.0f;
#pragma unroll
            for (int c = 0; c < 4; c++) {
                const int dx = c & 1;
                const int dy = c >> 1;
                const int xi = x0 + dx;
                const int yi = y0 + dy;
                if (xi >= 0 && xi < HW && yi >= 0 && yi < HW) {
                    const float wx = dx ? txf : (1.0f - txf);
                    const float wy = dy ? tyf : (1.0f - tyf);
                    const float wgt = wx * wy;
                    const int idx = ((base_n + yi * HW + xi) * M_ + m) * D_ + lane;
                    sk = fmaf(wgt, g_key[idx], sk);
                    sv = fmaf(wgt, g_value[idx], sv);
                }
            }
            svr[pi] = sv;
            float lg = qd * sk;
#pragma unroll
            for (int s = 16; s > 0; s >>= 1)
                lg += __shfl_xor_sync(0xffffffffu, lg, s);
            logits[pi] = lg * 0.17677669529663687f;   // 1/sqrt(32)
        }
    }

    // softmax over 16 points (same values in every lane)
    float mx = logits[0];
#pragma unroll
    for (int i = 1; i < 16; i++) mx = fmaxf(mx, logits[i]);
    float ssum = 0.0f;
#pragma unroll
    for (int i = 0; i < 16; i++) {
        logits[i] = __expf(logits[i] - mx);
        ssum += logits[i];
    }
    const float inv = 1.0f / ssum;
    float o = 0.0f;
#pragma unroll
    for (int i = 0; i < 16; i++) o = fmaf(logits[i], svr[i], o);

    g_att[(nq * M_ + m) * D_ + lane] = o * inv;
}

// ---------------------------------------------------------------------------
extern "C" void kernel_launch(void* const* d_in, const int* in_sizes, int n_in,
                              void* d_out, int out_size)
{
    const float* query = (const float*)d_in[0];   // [2,4000,256]
    const float* ref   = (const float*)d_in[1];   // [2,4000,4,2]
    const float* inp   = (const float*)d_in[2];   // [2,5440,256]
    // d_in[3], d_in[4]: spatial shapes / level starts (compile-time constants)
    const float* Wv   = (const float*)d_in[5];
    const float* bv   = (const float*)d_in[6];
    const float* Wk   = (const float*)d_in[7];
    const float* bk   = (const float*)d_in[8];
    const float* Wq   = (const float*)d_in[9];
    const float* bq   = (const float*)d_in[10];
    const float* Woff = (const float*)d_in[11];
    const float* boff = (const float*)d_in[12];
    const float* Wout = (const float*)d_in[13];
    const float* bout = (const float*)d_in[14];
    float* out = (float*)d_out;

    float *pv, *pk, *pq, *po, *pa;
    cudaGetSymbolAddress((void**)&pv, g_value);
    cudaGetSymbolAddress((void**)&pk, g_key);
    cudaGetSymbolAddress((void**)&pq, g_q);
    cudaGetSymbolAddress((void**)&po, g_off);
    cudaGetSymbolAddress((void**)&pa, g_att);

    dim3 blk(16, 16);
    const int rowsV = N_ * LIN_;   // 10880
    const int rowsQ = N_ * LQ_;    // 8000

    gemm_bias_256<<<dim3(4, rowsV / 64), blk>>>(inp,   Wv,   bv,   pv, rowsV);
    gemm_bias_256<<<dim3(4, rowsV / 64), blk>>>(inp,   Wk,   bk,   pk, rowsV);
    gemm_bias_256<<<dim3(4, rowsQ / 64), blk>>>(query, Wq,   bq,   pq, rowsQ);
    gemm_bias_256<<<dim3(4, rowsQ / 64), blk>>>(query, Woff, boff, po, rowsQ);

    const int nwarps = N_ * LQ_ * M_;          // 64000
    const int nblocks = (nwarps + 7) / 8;      // 8000 blocks of 8 warps
    sample_attn_kernel<<<nblocks, 256>>>(ref);

    gemm_bias_256<<<dim3(4, rowsQ / 64), blk>>>(pa, Wout, bout, out, rowsQ);
}

// round 2
// speedup vs baseline: 1.1921x; 1.1921x over previous
#include <cuda_runtime.h>
#include <cuda_fp16.h>
#include <math.h>

#define N_ 2
#define LQ_ 4000
#define C_ 256
#define M_ 8
#define L_ 4
#define P_ 4
#define D_ 32
#define LIN_ 5440   // 64*64 + 32*32 + 16*16 + 8*8

// Scratch (static device globals; no allocation allowed)
// kv: [N, Lin, M, 64] halves; channels 0..31 = key, 32..63 = value
__device__ __half g_kv [N_ * LIN_ * M_ * 64];
__device__ float  g_q  [N_ * LQ_ * C_];    // [N, Lq, M, D]
__device__ float  g_off[N_ * LQ_ * C_];    // [N, Lq, M*L*P*2]
__device__ float  g_att[N_ * LQ_ * C_];    // [N, Lq, M, D]

// ---------------------------------------------------------------------------
// GEMM: out[rows, 256] = A[rows,256] @ W[256,256] + bias
// BM=128, BN=64, BK=16, 256 threads, 8x4 register tile.
// MODE 0: float output, row stride 256
// MODE 1: half output into kv (key half),   col c -> (c>>5)*64 + (c&31)
// MODE 2: half output into kv (value half), col c -> (c>>5)*64 + (c&31) + 32
// ---------------------------------------------------------------------------
template<int MODE>
__global__ __launch_bounds__(256) void gemm_bias(
    const float* __restrict__ A, const float* __restrict__ W,
    const float* __restrict__ bias, void* __restrict__ outp, int rows)
{
    __shared__ float As[16][132];   // [k][m] transposed, padded
    __shared__ float Bs[16][68];    // [k][n]

    const int tid = threadIdx.x;
    const int tx = tid & 15;        // col group (4 cols)
    const int ty = tid >> 4;        // row group (8 rows)
    const int row0 = blockIdx.y * 128;
    const int col0 = blockIdx.x * 64;

    // A-tile loader: thread loads 8 consecutive k for one row m
    const int am  = tid >> 1;                    // 0..127
    const int kqA = (tid & 1) * 8;               // 0 or 8
    const float* Arow = A + (size_t)min(row0 + am, rows - 1) * 256;
    // B-tile loader: one float4
    const int kB = tid >> 4;                     // 0..15
    const int nB = (tid & 15) * 4;

    float4 a0 = *reinterpret_cast<const float4*>(&Arow[kqA]);
    float4 a1 = *reinterpret_cast<const float4*>(&Arow[kqA + 4]);
    float4 b0 = *reinterpret_cast<const float4*>(&W[kB * 256 + col0 + nB]);

    float acc[8][4];
#pragma unroll
    for (int i = 0; i < 8; i++)
#pragma unroll
        for (int j = 0; j < 4; j++) acc[i][j] = 0.0f;

    for (int k0 = 0; k0 < 256; k0 += 16) {
        // stage registers -> smem
        As[kqA + 0][am] = a0.x; As[kqA + 1][am] = a0.y;
        As[kqA + 2][am] = a0.z; As[kqA + 3][am] = a0.w;
        As[kqA + 4][am] = a1.x; As[kqA + 5][am] = a1.y;
        As[kqA + 6][am] = a1.z; As[kqA + 7][am] = a1.w;
        *reinterpret_cast<float4*>(&Bs[kB][nB]) = b0;
        __syncthreads();

        if (k0 + 16 < 256) {
            a0 = *reinterpret_cast<const float4*>(&Arow[k0 + 16 + kqA]);
            a1 = *reinterpret_cast<const float4*>(&Arow[k0 + 16 + kqA + 4]);
            b0 = *reinterpret_cast<const float4*>(&W[(k0 + 16 + kB) * 256 + col0 + nB]);
        }

#pragma unroll
        for (int k = 0; k < 16; k++) {
            float4 x0 = *reinterpret_cast<const float4*>(&As[k][ty * 8]);
            float4 x1 = *reinterpret_cast<const float4*>(&As[k][ty * 8 + 4]);
            float4 yv = *reinterpret_cast<const float4*>(&Bs[k][tx * 4]);
            float av[8] = {x0.x, x0.y, x0.z, x0.w, x1.x, x1.y, x1.z, x1.w};
            float bv[4] = {yv.x, yv.y, yv.z, yv.w};
#pragma unroll
            for (int i = 0; i < 8; i++)
#pragma unroll
                for (int j = 0; j < 4; j++)
                    acc[i][j] = fmaf(av[i], bv[j], acc[i][j]);
        }
        __syncthreads();
    }

    const int c0 = col0 + tx * 4;
    float4 bb = *reinterpret_cast<const float4*>(&bias[c0]);
#pragma unroll
    for (int i = 0; i < 8; i++) {
        const int r = row0 + ty * 8 + i;
        if (r < rows) {
            float4 v;
            v.x = acc[i][0] + bb.x; v.y = acc[i][1] + bb.y;
            v.z = acc[i][2] + bb.z; v.w = acc[i][3] + bb.w;
            if (MODE == 0) {
                *reinterpret_cast<float4*>(&((float*)outp)[(size_t)r * 256 + c0]) = v;
            } else {
                const int oc = ((c0 >> 5) << 6) + (c0 & 31) + (MODE == 2 ? 32 : 0);
                __half2* po = reinterpret_cast<__half2*>(&((__half*)outp)[(size_t)r * 512 + oc]);
                po[0] = __floats2half2_rn(v.x, v.y);
                po[1] = __floats2half2_rn(v.z, v.w);
            }
        }
    }
}

// ---------------------------------------------------------------------------
// Sampling + key-aware attention. One warp per (n, q, m).
// Lanes 0..15: key channels (2 per lane). Lanes 16..31: value channels.
// Each bilinear corner = ONE 128B coalesced warp load from interleaved kv.
// ---------------------------------------------------------------------------
__global__ __launch_bounds__(256) void sample_attn_kernel(
    const float* __restrict__ ref)   // [N, Lq, L, 2]
{
    const int w = blockIdx.x * 8 + (threadIdx.x >> 5);
    const int lane = threadIdx.x & 31;
    if (w >= N_ * LQ_ * M_) return;

    const int m  = w & 7;
    const int nq = w >> 3;           // n*Lq + q
    const int n  = nq / LQ_;

    const int is_v = lane >> 4;            // 0 = key lanes, 1 = value lanes
    const int cl = (lane & 15) * 2;        // channel pair

    float2 qd = make_float2(0.0f, 0.0f);
    if (!is_v) qd = *reinterpret_cast<const float2*>(&g_q[(nq * M_ + m) * D_ + cl]);

    const float* offp = g_off + nq * 256 + m * 32;
    const float* refp = ref + nq * 8;

    const int HWs[4]    = {64, 32, 16, 8};
    const int starts[4] = {0, 4096, 5120, 5376};

    float logits[16], sv0[16], sv1[16];

#pragma unroll
    for (int l = 0; l < L_; l++) {
        const float rx = refp[l * 2 + 0];
        const float ry = refp[l * 2 + 1];
        const int HW = HWs[l];
        const float fHW = (float)HW;
        const float fx = rx * fHW - 0.5f;
        const float fy = ry * fHW - 0.5f;
        const int base = (n * LIN_ + starts[l]) * M_ + m;   // kv row units

#pragma unroll
        for (int p = 0; p < P_; p++) {
            const int pi = l * 4 + p;
            const float x = fx + offp[pi * 2 + 0];
            const float y = fy + offp[pi * 2 + 1];
            const float x0f = floorf(x);
            const float y0f = floorf(y);
            const float txf = x - x0f;
            const float tyf = y - y0f;
            const int x0 = (int)x0f;
            const int y0 = (int)y0f;

            float s0 = 0.0f, s1 = 0.0f;
#pragma unroll
            for (int c = 0; c < 4; c++) {
                const int dx = c & 1;
                const int dy = c >> 1;
                const int xi = x0 + dx;
                const int yi = y0 + dy;
                if (xi >= 0 && xi < HW && yi >= 0 && yi < HW) {
                    const float wx = dx ? txf : (1.0f - txf);
                    const float wy = dy ? tyf : (1.0f - tyf);
                    const float wgt = wx * wy;
                    const int idx = (base + (yi * HW + xi) * M_) * 64 + lane * 2;
                    const float2 f = __half22float2(
                        *reinterpret_cast<const __half2*>(&g_kv[idx]));
                    s0 = fmaf(wgt, f.x, s0);
                    s1 = fmaf(wgt, f.y, s1);
                }
            }
            sv0[pi] = s0;
            sv1[pi] = s1;
            float part = is_v ? 0.0f : fmaf(qd.x, s0, qd.y * s1);
#pragma unroll
            for (int s = 16; s > 0; s >>= 1)
                part += __shfl_xor_sync(0xffffffffu, part, s);
            logits[pi] = part * 0.17677669529663687f;   // 1/sqrt(32)
        }
    }

    // softmax over 16 points (identical in all lanes)
    float mx = logits[0];
#pragma unroll
    for (int i = 1; i < 16; i++) mx = fmaxf(mx, logits[i]);
    float ssum = 0.0f;
#pragma unroll
    for (int i = 0; i < 16; i++) {
        logits[i] = __expf(logits[i] - mx);
        ssum += logits[i];
    }
    const float inv = 1.0f / ssum;
    float o0 = 0.0f, o1 = 0.0f;
#pragma unroll
    for (int i = 0; i < 16; i++) {
        o0 = fmaf(logits[i], sv0[i], o0);
        o1 = fmaf(logits[i], sv1[i], o1);
    }

    if (is_v) {
        float2 ov = make_float2(o0 * inv, o1 * inv);
        *reinterpret_cast<float2*>(&g_att[(nq * M_ + m) * D_ + cl]) = ov;
    }
}

// ---------------------------------------------------------------------------
extern "C" void kernel_launch(void* const* d_in, const int* in_sizes, int n_in,
                              void* d_out, int out_size)
{
    const float* query = (const float*)d_in[0];   // [2,4000,256]
    const float* ref   = (const float*)d_in[1];   // [2,4000,4,2]
    const float* inp   = (const float*)d_in[2];   // [2,5440,256]
    const float* Wv   = (const float*)d_in[5];
    const float* bv   = (const float*)d_in[6];
    const float* Wk   = (const float*)d_in[7];
    const float* bk   = (const float*)d_in[8];
    const float* Wq   = (const float*)d_in[9];
    const float* bq   = (const float*)d_in[10];
    const float* Woff = (const float*)d_in[11];
    const float* boff = (const float*)d_in[12];
    const float* Wout = (const float*)d_in[13];
    const float* bout = (const float*)d_in[14];
    float* out = (float*)d_out;

    void *pkv, *pq, *po, *pa;
    cudaGetSymbolAddress(&pkv, g_kv);
    cudaGetSymbolAddress(&pq,  g_q);
    cudaGetSymbolAddress(&po,  g_off);
    cudaGetSymbolAddress(&pa,  g_att);

    const int rowsV = N_ * LIN_;   // 10880 = 85*128
    const int rowsQ = N_ * LQ_;    // 8000  = 62.5*128
    const int gyV = rowsV / 128;         // 85
    const int gyQ = (rowsQ + 127) / 128; // 63

    gemm_bias<1><<<dim3(4, gyV), 256>>>(inp,   Wk,   bk,   pkv, rowsV);
    gemm_bias<2><<<dim3(4, gyV), 256>>>(inp,   Wv,   bv,   pkv, rowsV);
    gemm_bias<0><<<dim3(4, gyQ), 256>>>(query, Wq,   bq,   pq,  rowsQ);
    gemm_bias<0><<<dim3(4, gyQ), 256>>>(query, Woff, boff, po,  rowsQ);

    const int nwarps = N_ * LQ_ * M_;          // 64000
    sample_attn_kernel<<<(nwarps + 7) / 8, 256>>>(ref);

    gemm_bias<0><<<dim3(4, gyQ), 256>>>((const float*)pa, Wout, bout, out, rowsQ);
}

// round 3
// speedup vs baseline: 2.2163x; 1.8592x over previous
#include <cuda_runtime.h>
#include <cuda_fp16.h>
#include <cstdint>

#define N_ 2
#define LQ_ 4000
#define C_ 256
#define M_ 8
#define L_ 4
#define P_ 4
#define D_ 32
#define LIN_ 5440   // 64*64 + 32*32 + 16*16 + 8*8

// Scratch (static device globals; no allocation allowed)
__device__ __half g_kv [N_ * LIN_ * M_ * 64];  // [N,Lin,M,{k[32]|v[32]}]
__device__ float  g_q  [N_ * LQ_ * C_];
__device__ float  g_off[N_ * LQ_ * C_];
__device__ __half g_att[N_ * LQ_ * C_];
__device__ __half g_qh [N_ * LQ_ * C_];
__device__ __half g_inh[N_ * LIN_ * C_];
__device__ __half g_wh [5 * C_ * C_];          // Wk, Wv, Wq, Woff, Wout

// ---------------------------------------------------------------------------
// fp32 -> fp16 converters
// ---------------------------------------------------------------------------
__global__ void f2h_kernel(const float* __restrict__ s, __half* __restrict__ d, int n) {
    int i = (blockIdx.x * blockDim.x + threadIdx.x) * 4;
    if (i < n) {
        float4 v = *reinterpret_cast<const float4*>(s + i);
        __half2* p = reinterpret_cast<__half2*>(d + i);
        p[0] = __floats2half2_rn(v.x, v.y);
        p[1] = __floats2half2_rn(v.z, v.w);
    }
}

struct W5 { const float* w[5]; };
__global__ void f2h5_kernel(W5 ws, __half* __restrict__ d) {
    int which = blockIdx.y;
    int i = (blockIdx.x * blockDim.x + threadIdx.x) * 4;   // exact: 65536 elems
    const float* s = ws.w[which];
    float4 v = *reinterpret_cast<const float4*>(s + i);
    __half2* p = reinterpret_cast<__half2*>(d + which * (C_ * C_) + i);
    p[0] = __floats2half2_rn(v.x, v.y);
    p[1] = __floats2half2_rn(v.z, v.w);
}

__device__ __forceinline__ uint32_t smem_u32(const void* p) {
    return static_cast<uint32_t>(__cvta_generic_to_shared(p));
}

// ---------------------------------------------------------------------------
// HMMA GEMM: out[rows,256] = A[rows,256](fp16) @ W[256,256](fp16) + bias(fp32)
// BM=128 BN=64 BK=32, 8 warps (4m x 2n), warp tile 32x32 via m16n8k16.
// MODE 0: float out, stride 256.  MODE 1/2: half out into kv interleave.
// ---------------------------------------------------------------------------
template<int MODE>
__global__ __launch_bounds__(256) void gemm_mma(
    const __half* __restrict__ A, const __half* __restrict__ W,
    const float* __restrict__ bias, void* __restrict__ outp, int rows)
{
    __shared__ __half As[128 * 40];   // row r at r*40 halves (80B stride, conflict-free)
    __shared__ __half Bs[32 * 64];    // k row at k*64, chunk XOR-swizzled

    const int tid = threadIdx.x;
    const int lane = tid & 31;
    const int wm = (tid >> 5) & 3;
    const int wn = tid >> 7;
    const int row0 = blockIdx.y * 128;
    const int col0 = blockIdx.x * 64;

    // A loader: each thread 2x16B; rows ar, ar+64; chunk ac
    const int ar = tid >> 2;
    const int ac = tid & 3;
    const __half* Ag0 = A + (size_t)min(row0 + ar,      rows - 1) * 256 + ac * 8;
    const __half* Ag1 = A + (size_t)min(row0 + ar + 64, rows - 1) * 256 + ac * 8;
    // B loader: one 16B; k row bk, chunk bc
    const int bk = tid >> 3;
    const int bc = tid & 7;
    const __half* Bg = W + bk * 256 + col0 + bc * 8;

    uint4 pa0 = *reinterpret_cast<const uint4*>(Ag0);
    uint4 pa1 = *reinterpret_cast<const uint4*>(Ag1);
    uint4 pb  = *reinterpret_cast<const uint4*>(Bg);

    float acc[2][4][4];
#pragma unroll
    for (int mt = 0; mt < 2; mt++)
#pragma unroll
        for (int nt = 0; nt < 4; nt++)
#pragma unroll
            for (int i = 0; i < 4; i++) acc[mt][nt][i] = 0.0f;

    // ldmatrix lane addressing
    const int ltile = lane >> 3;
    const int ltr   = lane & 7;
    const int a_row_base = wm * 32 + (ltile & 1) * 8 + ltr;
    const int a_ch_off   = ltile >> 1;
    const int b_k_base   = (ltile & 1) * 8 + ltr;
    const int b_ch_off   = ltile >> 1;

    for (int k0 = 0; k0 < 256; k0 += 32) {
        *reinterpret_cast<uint4*>(&As[ar * 40 + ac * 8]) = pa0;
        *reinterpret_cast<uint4*>(&As[(ar + 64) * 40 + ac * 8]) = pa1;
        *reinterpret_cast<uint4*>(&Bs[bk * 64 + ((bc ^ (bk & 7)) * 8)]) = pb;
        __syncthreads();

        if (k0 + 32 < 256) {
            pa0 = *reinterpret_cast<const uint4*>(Ag0 + k0 + 32);
            pa1 = *reinterpret_cast<const uint4*>(Ag1 + k0 + 32);
            pb  = *reinterpret_cast<const uint4*>(Bg + (size_t)(k0 + 32) * 256);
        }

#pragma unroll
        for (int ks = 0; ks < 2; ks++) {
            uint32_t a[2][4], b[2][4];
#pragma unroll
            for (int mt = 0; mt < 2; mt++) {
                const int row = a_row_base + mt * 16;
                const int ch  = ks * 2 + a_ch_off;
                uint32_t addr = smem_u32(&As[row * 40 + ch * 8]);
                asm volatile(
                    "ldmatrix.sync.aligned.m8n8.x4.shared.b16 {%0,%1,%2,%3}, [%4];"
                    : "=r"(a[mt][0]), "=r"(a[mt][1]), "=r"(a[mt][2]), "=r"(a[mt][3])
                    : "r"(addr));
            }
#pragma unroll
            for (int p = 0; p < 2; p++) {
                const int k = ks * 16 + b_k_base;
                const int c = wn * 4 + p * 2 + b_ch_off;
                uint32_t addr = smem_u32(&Bs[k * 64 + ((c ^ (k & 7)) * 8)]);
                asm volatile(
                    "ldmatrix.sync.aligned.m8n8.x4.trans.shared.b16 {%0,%1,%2,%3}, [%4];"
                    : "=r"(b[p][0]), "=r"(b[p][1]), "=r"(b[p][2]), "=r"(b[p][3])
                    : "r"(addr));
            }
#pragma unroll
            for (int mt = 0; mt < 2; mt++)
#pragma unroll
                for (int nt = 0; nt < 4; nt++) {
                    const uint32_t bb0 = b[nt >> 1][(nt & 1) * 2 + 0];
                    const uint32_t bb1 = b[nt >> 1][(nt & 1) * 2 + 1];
                    asm volatile(
                        "mma.sync.aligned.m16n8k16.row.col.f32.f16.f16.f32 "
                        "{%0,%1,%2,%3}, {%4,%5,%6,%7}, {%8,%9}, {%0,%1,%2,%3};"
                        : "+f"(acc[mt][nt][0]), "+f"(acc[mt][nt][1]),
                          "+f"(acc[mt][nt][2]), "+f"(acc[mt][nt][3])
                        : "r"(a[mt][0]), "r"(a[mt][1]), "r"(a[mt][2]), "r"(a[mt][3]),
                          "r"(bb0), "r"(bb1));
                }
        }
        __syncthreads();
    }

    // epilogue
    const int g  = lane >> 2;
    const int qd = lane & 3;
#pragma unroll
    for (int mt = 0; mt < 2; mt++) {
        const int rlo = row0 + wm * 32 + mt * 16 + g;
        const int rhi = rlo + 8;
#pragma unroll
        for (int nt = 0; nt < 4; nt++) {
            const int n = col0 + wn * 32 + nt * 8 + qd * 2;
            const float2 bb = *reinterpret_cast<const float2*>(&bias[n]);
            if (MODE == 0) {
                float* o = (float*)outp;
                if (rlo < rows) {
                    float2 v = make_float2(acc[mt][nt][0] + bb.x, acc[mt][nt][1] + bb.y);
                    *reinterpret_cast<float2*>(&o[(size_t)rlo * 256 + n]) = v;
                }
                if (rhi < rows) {
                    float2 v = make_float2(acc[mt][nt][2] + bb.x, acc[mt][nt][3] + bb.y);
                    *reinterpret_cast<float2*>(&o[(size_t)rhi * 256 + n]) = v;
                }
            } else {
                const int oc = ((n >> 5) << 6) + (n & 31) + (MODE == 2 ? 32 : 0);
                __half* o = (__half*)outp;
                if (rlo < rows)
                    *reinterpret_cast<__half2*>(&o[(size_t)rlo * 512 + oc]) =
                        __floats2half2_rn(acc[mt][nt][0] + bb.x, acc[mt][nt][1] + bb.y);
                if (rhi < rows)
                    *reinterpret_cast<__half2*>(&o[(size_t)rhi * 512 + oc]) =
                        __floats2half2_rn(acc[mt][nt][2] + bb.x, acc[mt][nt][3] + bb.y);
            }
        }
    }
}

// ---------------------------------------------------------------------------
// Sampling + key-aware attention. One warp per (n, q, m).
// Lanes 0..15: key channels; lanes 16..31: value channels.
// ---------------------------------------------------------------------------
__global__ __launch_bounds__(256) void sample_attn_kernel(
    const float* __restrict__ ref)   // [N, Lq, L, 2]
{
    const int w = blockIdx.x * 8 + (threadIdx.x >> 5);
    const int lane = threadIdx.x & 31;
    if (w >= N_ * LQ_ * M_) return;

    const int m  = w & 7;
    const int nq = w >> 3;
    const int n  = nq / LQ_;

    const int is_v = lane >> 4;
    const int cl = (lane & 15) * 2;

    float2 qd = make_float2(0.0f, 0.0f);
    if (!is_v) qd = *reinterpret_cast<const float2*>(&g_q[(nq * M_ + m) * D_ + cl]);

    const float* offp = g_off + nq * 256 + m * 32;
    const float* refp = ref + nq * 8;

    const int HWs[4]    = {64, 32, 16, 8};
    const int starts[4] = {0, 4096, 5120, 5376};

    float logits[16], sv0[16], sv1[16];

#pragma unroll
    for (int l = 0; l < L_; l++) {
        const float rx = refp[l * 2 + 0];
        const float ry = refp[l * 2 + 1];
        const int HW = HWs[l];
        const float fHW = (float)HW;
        const float fx = rx * fHW - 0.5f;
        const float fy = ry * fHW - 0.5f;
        const int base = (n * LIN_ + starts[l]) * M_ + m;

#pragma unroll
        for (int p = 0; p < P_; p++) {
            const int pi = l * 4 + p;
            const float x = fx + offp[pi * 2 + 0];
            const float y = fy + offp[pi * 2 + 1];
            const float x0f = floorf(x);
            const float y0f = floorf(y);
            const float txf = x - x0f;
            const float tyf = y - y0f;
            const int x0 = (int)x0f;
            const int y0 = (int)y0f;

            float s0 = 0.0f, s1 = 0.0f;
#pragma unroll
            for (int c = 0; c < 4; c++) {
                const int dx = c & 1;
                const int dy = c >> 1;
                const int xi = x0 + dx;
                const int yi = y0 + dy;
                if (xi >= 0 && xi < HW && yi >= 0 && yi < HW) {
                    const float wx = dx ? txf : (1.0f - txf);
                    const float wy = dy ? tyf : (1.0f - tyf);
                    const float wgt = wx * wy;
                    const int idx = (base + (yi * HW + xi) * M_) * 64 + lane * 2;
                    const float2 f = __half22float2(
                        *reinterpret_cast<const __half2*>(&g_kv[idx]));
                    s0 = fmaf(wgt, f.x, s0);
                    s1 = fmaf(wgt, f.y, s1);
                }
            }
            sv0[pi] = s0;
            sv1[pi] = s1;
            float part = is_v ? 0.0f : fmaf(qd.x, s0, qd.y * s1);
#pragma unroll
            for (int s = 16; s > 0; s >>= 1)
                part += __shfl_xor_sync(0xffffffffu, part, s);
            logits[pi] = part * 0.17677669529663687f;
        }
    }

    float mx = logits[0];
#pragma unroll
    for (int i = 1; i < 16; i++) mx = fmaxf(mx, logits[i]);
    float ssum = 0.0f;
#pragma unroll
    for (int i = 0; i < 16; i++) {
        logits[i] = __expf(logits[i] - mx);
        ssum += logits[i];
    }
    const float inv = 1.0f / ssum;
    float o0 = 0.0f, o1 = 0.0f;
#pragma unroll
    for (int i = 0; i < 16; i++) {
        o0 = fmaf(logits[i], sv0[i], o0);
        o1 = fmaf(logits[i], sv1[i], o1);
    }

    if (is_v)
        *reinterpret_cast<__half2*>(&g_att[(nq * M_ + m) * D_ + cl]) =
            __floats2half2_rn(o0 * inv, o1 * inv);
}

// ---------------------------------------------------------------------------
extern "C" void kernel_launch(void* const* d_in, const int* in_sizes, int n_in,
                              void* d_out, int out_size)
{
    const float* query = (const float*)d_in[0];
    const float* ref   = (const float*)d_in[1];
    const float* inp   = (const float*)d_in[2];
    const float* Wv   = (const float*)d_in[5];
    const float* bv   = (const float*)d_in[6];
    const float* Wk   = (const float*)d_in[7];
    const float* bk   = (const float*)d_in[8];
    const float* Wq   = (const float*)d_in[9];
    const float* bq   = (const float*)d_in[10];
    const float* Woff = (const float*)d_in[11];
    const float* boff = (const float*)d_in[12];
    const float* Wout = (const float*)d_in[13];
    const float* bout = (const float*)d_in[14];
    float* out = (float*)d_out;

    void *pkv, *pq, *po, *pa, *pqh, *pinh, *pwh;
    cudaGetSymbolAddress(&pkv,  g_kv);
    cudaGetSymbolAddress(&pq,   g_q);
    cudaGetSymbolAddress(&po,   g_off);
    cudaGetSymbolAddress(&pa,   g_att);
    cudaGetSymbolAddress(&pqh,  g_qh);
    cudaGetSymbolAddress(&pinh, g_inh);
    cudaGetSymbolAddress(&pwh,  g_wh);

    const int rowsV = N_ * LIN_;   // 10880
    const int rowsQ = N_ * LQ_;    // 8000
    const int gyV = rowsV / 128;          // 85
    const int gyQ = (rowsQ + 127) / 128;  // 63

    const int nQ = rowsQ * 256;    // 2,048,000
    const int nV = rowsV * 256;    // 2,785,280

    f2h_kernel<<<nV / 4 / 256, 256>>>(inp,   (__half*)pinh, nV);
    f2h_kernel<<<nQ / 4 / 256, 256>>>(query, (__half*)pqh,  nQ);
    W5 ws; ws.w[0] = Wk; ws.w[1] = Wv; ws.w[2] = Wq; ws.w[3] = Woff; ws.w[4] = Wout;
    f2h5_kernel<<<dim3(64, 5), 256>>>(ws, (__half*)pwh);

    const __half* wh = (const __half*)pwh;
    gemm_mma<1><<<dim3(4, gyV), 256>>>((const __half*)pinh, wh + 0 * 65536, bk,   pkv, rowsV);
    gemm_mma<2><<<dim3(4, gyV), 256>>>((const __half*)pinh, wh + 1 * 65536, bv,   pkv, rowsV);
    gemm_mma<0><<<dim3(4, gyQ), 256>>>((const __half*)pqh,  wh + 2 * 65536, bq,   pq,  rowsQ);
    gemm_mma<0><<<dim3(4, gyQ), 256>>>((const __half*)pqh,  wh + 3 * 65536, boff, po,  rowsQ);

    const int nwarps = N_ * LQ_ * M_;          // 64000
    sample_attn_kernel<<<(nwarps + 7) / 8, 256>>>(ref);

    gemm_mma<0><<<dim3(4, gyQ), 256>>>((const __half*)pa, wh + 4 * 65536, bout, out, rowsQ);
}